// round 1
// baseline (speedup 1.0000x reference)
#include <cuda_runtime.h>
#include <math.h>

// Problem constants (shapes fixed by setup_inputs)
#define BATCH 64
#define IMH 512
#define IMW 512
#define NC 64          // cells per spatial dim (512/8)
#define NORI 9
#define NB 63          // blocks per spatial dim (NC-1)
#define OUT_PER_B (NB*NB*2*2*NORI)   // 142884

// Cell histogram scratch: [B][NC][NC][9] = 9.4 MB
__device__ float g_hist[(size_t)BATCH * NC * NC * NORI];

// ---------------------------------------------------------------------------
// Kernel 1: gray -> gradients -> orientation bin -> 8x8 cell histograms
// One block = 64x64 pixel tile (8x8 cells), 256 threads (4 threads per cell,
// each owns a 4x4 pixel quadrant). Gray staged in smem with 1-pixel halo.
// ---------------------------------------------------------------------------
__global__ __launch_bounds__(256) void hog_cells_kernel(const float* __restrict__ x)
{
    __shared__ float sm[66][67];   // 66x66 gray halo tile, padded stride

    const int tx = blockIdx.x;     // tile col (0..7)
    const int ty = blockIdx.y;     // tile row (0..7)
    const int b  = blockIdx.z;
    const int tid = threadIdx.x;
    const int oy = ty * 64;
    const int ox = tx * 64;

    // Phase 1: cooperative load of gray halo tile (66x66)
    for (int i = tid; i < 66 * 66; i += 256) {
        const int lr = i / 66;
        const int lc = i - lr * 66;
        const int h = oy - 1 + lr;
        const int w = ox - 1 + lc;
        float g = 0.0f;
        if (h >= 0 && h < IMH && w >= 0 && w < IMW) {
            const float* p = x + (((size_t)b * IMH + h) * IMW + w) * 3;
            g = 0.2125f * p[0] + 0.7154f * p[1] + 0.0721f * p[2];
        }
        sm[lr][lc] = g;
    }
    __syncthreads();

    // Phase 2: each thread handles a 4x4 quadrant of one cell
    const int cell = tid >> 2;          // 0..63
    const int sub  = tid & 3;           // quadrant
    const int cy = cell >> 3;
    const int cx = cell & 7;
    const int py0 = cy * 8 + (sub >> 1) * 4;
    const int px0 = cx * 8 + (sub & 1) * 4;

    float hacc[NORI];
#pragma unroll
    for (int o = 0; o < NORI; o++) hacc[o] = 0.0f;

#pragma unroll
    for (int dy = 0; dy < 4; dy++) {
#pragma unroll
        for (int dx = 0; dx < 4; dx++) {
            const int r = py0 + dy;     // tile-local pixel row
            const int c = px0 + dx;
            const int h = oy + r;       // global
            const int w = ox + c;
            // g_row[h] = gray[h+1]-gray[h-1] (0 at image borders)
            float gr = (h > 0 && h < IMH - 1) ? (sm[r + 2][c + 1] - sm[r][c + 1]) : 0.0f;
            float gc = (w > 0 && w < IMW - 1) ? (sm[r + 1][c + 2] - sm[r + 1][c]) : 0.0f;
            float mag = sqrtf(gr * gr + gc * gc);

            // canonicalize to upper half-plane: theta = atan2(gr,gc) mod 180
            float yy = gr, xx = gc;
            if (yy < 0.0f || (yy == 0.0f && xx < 0.0f)) { yy = -yy; xx = -xx; }

            // bin = #{k in 1..8 : theta >= 20k}, via sign of sin(20k - theta)
            int bin = 0;
            bin += (xx * 0.3420201433f - yy * 0.9396926208f <= 0.0f);  // 20
            bin += (xx * 0.6427876097f - yy * 0.7660444431f <= 0.0f);  // 40
            bin += (xx * 0.8660254038f - yy * 0.5000000000f <= 0.0f);  // 60
            bin += (xx * 0.9848077530f - yy * 0.1736481777f <= 0.0f);  // 80
            bin += (xx * 0.9848077530f + yy * 0.1736481777f <= 0.0f);  // 100
            bin += (xx * 0.8660254038f + yy * 0.5000000000f <= 0.0f);  // 120
            bin += (xx * 0.6427876097f + yy * 0.7660444431f <= 0.0f);  // 140
            bin += (xx * 0.3420201433f + yy * 0.9396926208f <= 0.0f);  // 160

#pragma unroll
            for (int o = 0; o < NORI; o++)
                hacc[o] += (bin == o) ? mag : 0.0f;
        }
    }

    // Reduce the 4 quadrant threads of each cell (lanes tid&~3 .. +3, same warp)
#pragma unroll
    for (int o = 0; o < NORI; o++) {
        hacc[o] += __shfl_xor_sync(0xffffffffu, hacc[o], 1);
        hacc[o] += __shfl_xor_sync(0xffffffffu, hacc[o], 2);
    }

    if (sub == 0) {
        const int cellY = ty * 8 + cy;
        const int cellX = tx * 8 + cx;
        float* hp = g_hist + (((size_t)b * NC + cellY) * NC + cellX) * NORI;
#pragma unroll
        for (int o = 0; o < NORI; o++)
            hp[o] = hacc[o] * 0.015625f;   // / cell_area (64)
    }
}

// ---------------------------------------------------------------------------
// Kernel 2: 2x2 block gather + double L2-hys normalization + coalesced store
// One thread per block position (63*63 per batch); smem-staged output.
// ---------------------------------------------------------------------------
__global__ __launch_bounds__(256) void hog_blocks_kernel(float* __restrict__ out)
{
    __shared__ float buf[256 * 36];    // 36 KB

    const int b  = blockIdx.y;
    const int p0 = blockIdx.x * 256;
    const int tid = threadIdx.x;
    const int p = p0 + tid;

    if (p < NB * NB) {
        const int rp = p / NB;
        const int cp = p - rp * NB;

        float v[36];
        float ss = 1e-10f;             // EPS^2
#pragma unroll
        for (int dr = 0; dr < 2; dr++) {
#pragma unroll
            for (int dc = 0; dc < 2; dc++) {
                const float* hp = g_hist +
                    (((size_t)b * NC + (rp + dr)) * NC + (cp + dc)) * NORI;
#pragma unroll
                for (int o = 0; o < NORI; o++) {
                    const float t = hp[o];
                    v[(dr * 2 + dc) * NORI + o] = t;
                    ss += t * t;
                }
            }
        }
        const float n1 = rsqrtf(ss);
        float ss2 = 1e-10f;
#pragma unroll
        for (int j = 0; j < 36; j++) {
            const float t = fminf(v[j] * n1, 0.2f);
            v[j] = t;
            ss2 += t * t;
        }
        const float n2 = rsqrtf(ss2);
#pragma unroll
        for (int j = 0; j < 36; j++)
            buf[tid * 36 + j] = v[j] * n2;
    }
    __syncthreads();

    const int npos = min(256, NB * NB - p0);
    const int count = npos * 36;
    const size_t base = (size_t)b * OUT_PER_B + (size_t)p0 * 36;
    for (int i = tid; i < count; i += 256)
        out[base + i] = buf[i];
}

extern "C" void kernel_launch(void* const* d_in, const int* in_sizes, int n_in,
                              void* d_out, int out_size)
{
    const float* x = (const float*)d_in[0];
    float* out = (float*)d_out;

    dim3 g1(IMW / 64, IMH / 64, BATCH);     // (8, 8, 64)
    hog_cells_kernel<<<g1, 256>>>(x);

    dim3 g2((NB * NB + 255) / 256, BATCH);  // (16, 64)
    hog_blocks_kernel<<<g2, 256>>>(out);
}

// round 2
// speedup vs baseline: 1.4325x; 1.4325x over previous
#include <cuda_runtime.h>
#include <math.h>

#define BATCH 64
#define IMH 512
#define IMW 512
#define NC 64
#define NORI 9
#define NB 63
#define OUT_PER_B (NB*NB*2*2*NORI)   // 142884

// Cell histogram scratch: [B][NC][NC][9] = 9.4 MB
__device__ float g_hist[(size_t)BATCH * NC * NC * NORI];

__device__ __forceinline__ float fsqrt_approx(float x) {
    float r;
    asm("sqrt.approx.f32 %0, %1;" : "=f"(r) : "f"(x));
    return r;
}

// ---------------------------------------------------------------------------
// Kernel 1: gray -> gradients -> orientation bin -> 8x8 cell histograms
// Block = 64x64 pixel tile, 256 threads, thread = 4x4 quadrant of one cell.
// Mirrored halo kills border predicates; private smem hist kills the 9-way
// predicated accumulate; sqrt.approx kills the IEEE sqrt sequence.
// ---------------------------------------------------------------------------
__global__ __launch_bounds__(256) void hog_cells_kernel(const float* __restrict__ x)
{
    __shared__ float sm[66][67];        // gray halo tile
    __shared__ float smh[256][NORI];    // per-thread private histograms

    const int tx = blockIdx.x;
    const int ty = blockIdx.y;
    const int b  = blockIdx.z;
    const int tid = threadIdx.x;
    const int oy = ty * 64;
    const int ox = tx * 64;

    // zero private hist
#pragma unroll
    for (int o = 0; o < NORI; o++) smh[tid][o] = 0.0f;

    // Phase 1: gray halo load with mirror at image borders
    // gray[-1]:=gray[1], gray[512]:=gray[510]  =>  central diff == 0 at borders
    for (int i = tid; i < 66 * 66; i += 256) {
        const int lr = i / 66;
        const int lc = i - lr * 66;
        int h = oy - 1 + lr;
        int w = ox - 1 + lc;
        h = (h < 0) ? 1 : ((h > IMH - 1) ? IMH - 2 : h);
        w = (w < 0) ? 1 : ((w > IMW - 1) ? IMW - 2 : w);
        const float* p = x + (((size_t)b * IMH + h) * IMW + w) * 3;
        sm[lr][lc] = 0.2125f * p[0] + 0.7154f * p[1] + 0.0721f * p[2];
    }
    __syncthreads();

    // Phase 2: 4x4 pixel quadrant per thread
    const int cell = tid >> 2;
    const int sub  = tid & 3;
    const int cy = cell >> 3;
    const int cx = cell & 7;
    const int py0 = cy * 8 + (sub >> 1) * 4;
    const int px0 = cx * 8 + (sub & 1) * 4;

    float* hist = smh[tid];

#pragma unroll
    for (int dy = 0; dy < 4; dy++) {
#pragma unroll
        for (int dx = 0; dx < 4; dx++) {
            const int r = py0 + dy;
            const int c = px0 + dx;
            const float gr = sm[r + 2][c + 1] - sm[r][c + 1];
            const float gc = sm[r + 1][c + 2] - sm[r + 1][c];
            const float mag = fsqrt_approx(gr * gr + gc * gc);

            // canonicalize to upper half-plane (theta in [0,180))
            const bool flip = (gr < 0.0f) || (gr == 0.0f && gc < 0.0f);
            const float yy = flip ? -gr : gr;
            const float xx = flip ? -gc : gc;

            // bin = #{k in 1..8 : theta > 20k}, via sign of sin(20k)-boundary test
            const float s1 = xx * 0.3420201433f - yy * 0.9396926208f;
            const float s2 = xx * 0.6427876097f - yy * 0.7660444431f;
            const float s3 = xx * 0.8660254038f - yy * 0.5000000000f;
            const float s4 = xx * 0.9848077530f - yy * 0.1736481777f;
            const float s5 = xx * 0.9848077530f + yy * 0.1736481777f;
            const float s6 = xx * 0.8660254038f + yy * 0.5000000000f;
            const float s7 = xx * 0.6427876097f + yy * 0.7660444431f;
            const float s8 = xx * 0.3420201433f + yy * 0.9396926208f;
            const int bin = (int)(__float_as_uint(s1) >> 31)
                          + (int)(__float_as_uint(s2) >> 31)
                          + (int)(__float_as_uint(s3) >> 31)
                          + (int)(__float_as_uint(s4) >> 31)
                          + (int)(__float_as_uint(s5) >> 31)
                          + (int)(__float_as_uint(s6) >> 31)
                          + (int)(__float_as_uint(s7) >> 31)
                          + (int)(__float_as_uint(s8) >> 31);

            hist[bin] += mag;
        }
    }

    __syncwarp();

    // Phase 3: reduce the 4 quadrant threads of each cell (adjacent smh rows)
    if (sub == 0) {
        const int cellY = ty * 8 + cy;
        const int cellX = tx * 8 + cx;
        float* hp = g_hist + (((size_t)b * NC + cellY) * NC + cellX) * NORI;
#pragma unroll
        for (int o = 0; o < NORI; o++) {
            const float s = smh[tid][o] + smh[tid + 1][o]
                          + smh[tid + 2][o] + smh[tid + 3][o];
            hp[o] = s * 0.015625f;   // / 64 (cell area)
        }
    }
}

// ---------------------------------------------------------------------------
// Kernel 2: 2x2 block gather + double L2-hys normalization.
// Tile = 16x16 block positions; 17x17x9 cell hists staged in smem via
// coalesced row-segment loads; output staged in smem for coalesced stores.
// ---------------------------------------------------------------------------
#define T2 16
__global__ __launch_bounds__(256) void hog_blocks_kernel(float* __restrict__ out)
{
    __shared__ float ct[17 * 17 * NORI];        // 10404 B
    __shared__ float buf[T2 * T2 * 36];         // 36864 B

    const int b   = blockIdx.z;
    const int rp0 = blockIdx.y * T2;
    const int cp0 = blockIdx.x * T2;
    const int tid = threadIdx.x;

    // Phase A: coalesced load of 17 cell rows x (17 cells * 9) floats
    const int rowlen = 17 * NORI;                 // 153
    const int maxj = (NC - cp0) * NORI;           // valid floats per row
    for (int i = tid; i < 17 * rowlen; i += 256) {
        const int cr = i / rowlen;
        const int j  = i - cr * rowlen;
        const int gy = rp0 + cr;
        float v = 0.0f;
        if (gy < NC && j < maxj)
            v = g_hist[(((size_t)b * NC + gy) * NC + cp0) * NORI + j];
        ct[i] = v;
    }
    __syncthreads();

    // Phase B: one thread per block position
    const int lr = tid >> 4;
    const int lc = tid & 15;
    const int rp = rp0 + lr;
    const int cp = cp0 + lc;

    if (rp < NB && cp < NB) {
        float v[36];
        float ss = 1e-10f;    // EPS^2
#pragma unroll
        for (int dr = 0; dr < 2; dr++) {
#pragma unroll
            for (int dc = 0; dc < 2; dc++) {
                const float* hp = &ct[((lr + dr) * 17 + (lc + dc)) * NORI];
#pragma unroll
                for (int o = 0; o < NORI; o++) {
                    const float t = hp[o];
                    v[(dr * 2 + dc) * NORI + o] = t;
                    ss += t * t;
                }
            }
        }
        const float n1 = rsqrtf(ss);
        float ss2 = 1e-10f;
#pragma unroll
        for (int j = 0; j < 36; j++) {
            const float t = fminf(v[j] * n1, 0.2f);
            v[j] = t;
            ss2 += t * t;
        }
        const float n2 = rsqrtf(ss2);
#pragma unroll
        for (int j = 0; j < 36; j++)
            buf[tid * 36 + j] = v[j] * n2;
    }
    __syncthreads();

    // Phase C: coalesced store, one tile-row (<=16 positions * 36) at a time
    const int rows = min(T2, NB - rp0);
    const int cols = min(T2, NB - cp0);
    const int n = cols * 36;
    for (int r = 0; r < rows; r++) {
        const size_t base = (size_t)b * OUT_PER_B + ((size_t)(rp0 + r) * NB + cp0) * 36;
        const float* src = &buf[r * T2 * 36];
        for (int i = tid; i < n; i += 256)
            out[base + i] = src[i];
    }
}

extern "C" void kernel_launch(void* const* d_in, const int* in_sizes, int n_in,
                              void* d_out, int out_size)
{
    const float* x = (const float*)d_in[0];
    float* out = (float*)d_out;

    dim3 g1(IMW / 64, IMH / 64, BATCH);              // (8, 8, 64)
    hog_cells_kernel<<<g1, 256>>>(x);

    dim3 g2((NB + T2 - 1) / T2, (NB + T2 - 1) / T2, BATCH);  // (4, 4, 64)
    hog_blocks_kernel<<<g2, 256>>>(out);
}

// round 3
// speedup vs baseline: 1.4569x; 1.0171x over previous
#include <cuda_runtime.h>
#include <math.h>

#define BATCH 64
#define IMH 512
#define IMW 512
#define NC 64
#define NORI 9
#define NB 63
#define OUT_PER_B (NB*NB*2*2*NORI)   // 142884

// Cell histogram scratch: [B][NC][NC][9] = 9.4 MB
__device__ float g_hist[(size_t)BATCH * NC * NC * NORI];

__device__ __forceinline__ float fsqrt_approx(float x) {
    float r;
    asm("sqrt.approx.f32 %0, %1;" : "=f"(r) : "f"(x));
    return r;
}

// ---------------------------------------------------------------------------
// Kernel 1: gray -> gradients -> orientation bin -> 8x8 cell histograms
// Block = 64x64 pixel tile, 256 threads, thread = 4x4 quadrant of one cell.
// Mirrored halo kills border predicates; private smem hist kills the 9-way
// predicated accumulate; sqrt.approx kills the IEEE sqrt sequence.
// ---------------------------------------------------------------------------
__global__ __launch_bounds__(256) void hog_cells_kernel(const float* __restrict__ x)
{
    __shared__ float sm[66][67];        // gray halo tile
    __shared__ float smh[256][NORI];    // per-thread private histograms

    const int tx = blockIdx.x;
    const int ty = blockIdx.y;
    const int b  = blockIdx.z;
    const int tid = threadIdx.x;
    const int oy = ty * 64;
    const int ox = tx * 64;

    // zero private hist
#pragma unroll
    for (int o = 0; o < NORI; o++) smh[tid][o] = 0.0f;

    // Phase 1: gray halo load with mirror at image borders
    // gray[-1]:=gray[1], gray[512]:=gray[510]  =>  central diff == 0 at borders
    for (int i = tid; i < 66 * 66; i += 256) {
        const int lr = i / 66;
        const int lc = i - lr * 66;
        int h = oy - 1 + lr;
        int w = ox - 1 + lc;
        h = (h < 0) ? 1 : ((h > IMH - 1) ? IMH - 2 : h);
        w = (w < 0) ? 1 : ((w > IMW - 1) ? IMW - 2 : w);
        const float* p = x + (((size_t)b * IMH + h) * IMW + w) * 3;
        sm[lr][lc] = 0.2125f * p[0] + 0.7154f * p[1] + 0.0721f * p[2];
    }
    __syncthreads();

    // Phase 2: 4x4 pixel quadrant per thread
    const int cell = tid >> 2;
    const int sub  = tid & 3;
    const int cy = cell >> 3;
    const int cx = cell & 7;
    const int py0 = cy * 8 + (sub >> 1) * 4;
    const int px0 = cx * 8 + (sub & 1) * 4;

    float* hist = smh[tid];

#pragma unroll
    for (int dy = 0; dy < 4; dy++) {
#pragma unroll
        for (int dx = 0; dx < 4; dx++) {
            const int r = py0 + dy;
            const int c = px0 + dx;
            const float gr = sm[r + 2][c + 1] - sm[r][c + 1];
            const float gc = sm[r + 1][c + 2] - sm[r + 1][c];
            const float mag = fsqrt_approx(gr * gr + gc * gc);

            // canonicalize to upper half-plane (theta in [0,180))
            const bool flip = (gr < 0.0f) || (gr == 0.0f && gc < 0.0f);
            const float yy = flip ? -gr : gr;
            const float xx = flip ? -gc : gc;

            // bin = #{k in 1..8 : theta > 20k}, via sign of sin(20k)-boundary test
            const float s1 = xx * 0.3420201433f - yy * 0.9396926208f;
            const float s2 = xx * 0.6427876097f - yy * 0.7660444431f;
            const float s3 = xx * 0.8660254038f - yy * 0.5000000000f;
            const float s4 = xx * 0.9848077530f - yy * 0.1736481777f;
            const float s5 = xx * 0.9848077530f + yy * 0.1736481777f;
            const float s6 = xx * 0.8660254038f + yy * 0.5000000000f;
            const float s7 = xx * 0.6427876097f + yy * 0.7660444431f;
            const float s8 = xx * 0.3420201433f + yy * 0.9396926208f;
            const int bin = (int)(__float_as_uint(s1) >> 31)
                          + (int)(__float_as_uint(s2) >> 31)
                          + (int)(__float_as_uint(s3) >> 31)
                          + (int)(__float_as_uint(s4) >> 31)
                          + (int)(__float_as_uint(s5) >> 31)
                          + (int)(__float_as_uint(s6) >> 31)
                          + (int)(__float_as_uint(s7) >> 31)
                          + (int)(__float_as_uint(s8) >> 31);

            hist[bin] += mag;
        }
    }

    __syncwarp();

    // Phase 3: reduce the 4 quadrant threads of each cell (adjacent smh rows)
    if (sub == 0) {
        const int cellY = ty * 8 + cy;
        const int cellX = tx * 8 + cx;
        float* hp = g_hist + (((size_t)b * NC + cellY) * NC + cellX) * NORI;
#pragma unroll
        for (int o = 0; o < NORI; o++) {
            const float s = smh[tid][o] + smh[tid + 1][o]
                          + smh[tid + 2][o] + smh[tid + 3][o];
            hp[o] = s * 0.015625f;   // / 64 (cell area)
        }
    }
}

// ---------------------------------------------------------------------------
// Kernel 2: 2x2 block gather + double L2-hys normalization.
// Tile = 16x16 block positions; 17x17x9 cell hists staged in smem via
// coalesced row-segment loads; output staged in smem for coalesced stores.
// ---------------------------------------------------------------------------
#define T2 16
__global__ __launch_bounds__(256) void hog_blocks_kernel(float* __restrict__ out)
{
    __shared__ float ct[17 * 17 * NORI];        // 10404 B
    __shared__ float buf[T2 * T2 * 36];         // 36864 B

    const int b   = blockIdx.z;
    const int rp0 = blockIdx.y * T2;
    const int cp0 = blockIdx.x * T2;
    const int tid = threadIdx.x;

    // Phase A: coalesced load of 17 cell rows x (17 cells * 9) floats
    const int rowlen = 17 * NORI;                 // 153
    const int maxj = (NC - cp0) * NORI;           // valid floats per row
    for (int i = tid; i < 17 * rowlen; i += 256) {
        const int cr = i / rowlen;
        const int j  = i - cr * rowlen;
        const int gy = rp0 + cr;
        float v = 0.0f;
        if (gy < NC && j < maxj)
            v = g_hist[(((size_t)b * NC + gy) * NC + cp0) * NORI + j];
        ct[i] = v;
    }
    __syncthreads();

    // Phase B: one thread per block position
    const int lr = tid >> 4;
    const int lc = tid & 15;
    const int rp = rp0 + lr;
    const int cp = cp0 + lc;

    if (rp < NB && cp < NB) {
        float v[36];
        float ss = 1e-10f;    // EPS^2
#pragma unroll
        for (int dr = 0; dr < 2; dr++) {
#pragma unroll
            for (int dc = 0; dc < 2; dc++) {
                const float* hp = &ct[((lr + dr) * 17 + (lc + dc)) * NORI];
#pragma unroll
                for (int o = 0; o < NORI; o++) {
                    const float t = hp[o];
                    v[(dr * 2 + dc) * NORI + o] = t;
                    ss += t * t;
                }
            }
        }
        const float n1 = rsqrtf(ss);
        float ss2 = 1e-10f;
#pragma unroll
        for (int j = 0; j < 36; j++) {
            const float t = fminf(v[j] * n1, 0.2f);
            v[j] = t;
            ss2 += t * t;
        }
        const float n2 = rsqrtf(ss2);
#pragma unroll
        for (int j = 0; j < 36; j++)
            buf[tid * 36 + j] = v[j] * n2;
    }
    __syncthreads();

    // Phase C: coalesced store, one tile-row (<=16 positions * 36) at a time
    const int rows = min(T2, NB - rp0);
    const int cols = min(T2, NB - cp0);
    const int n = cols * 36;
    for (int r = 0; r < rows; r++) {
        const size_t base = (size_t)b * OUT_PER_B + ((size_t)(rp0 + r) * NB + cp0) * 36;
        const float* src = &buf[r * T2 * 36];
        for (int i = tid; i < n; i += 256)
            out[base + i] = src[i];
    }
}

extern "C" void kernel_launch(void* const* d_in, const int* in_sizes, int n_in,
                              void* d_out, int out_size)
{
    const float* x = (const float*)d_in[0];
    float* out = (float*)d_out;

    dim3 g1(IMW / 64, IMH / 64, BATCH);              // (8, 8, 64)
    hog_cells_kernel<<<g1, 256>>>(x);

    dim3 g2((NB + T2 - 1) / T2, (NB + T2 - 1) / T2, BATCH);  // (4, 4, 64)
    hog_blocks_kernel<<<g2, 256>>>(out);
}

// round 4
// speedup vs baseline: 1.5337x; 1.0527x over previous
#include <cuda_runtime.h>
#include <math.h>

#define BATCH 64
#define IMH 512
#define IMW 512
#define NC 64
#define NORI 9
#define NB 63
#define OUT_PER_B (NB*NB*2*2*NORI)   // 142884

// Transposed cell histogram scratch: [B][9][NC][NC] = 9.4 MB (L2-resident)
__device__ float g_hist[(size_t)BATCH * NORI * NC * NC];

__device__ __forceinline__ float fsqrt_approx(float v) {
    float r;
    asm("sqrt.approx.f32 %0, %1;" : "=f"(r) : "f"(v));
    return r;
}

// ---------------------------------------------------------------------------
// Kernel 1: gray -> gradients -> orientation cumsum -> 8x8 cell histograms
// Block = 64x64 pixel tile, 256 threads; thread = 4x4 quadrant of one cell.
// Vectorized LDG.128 gray load; 6x6 register patch; 9 register cumulative
// accumulators (monotone bin predicates) - no smem histogram RMW chain.
// ---------------------------------------------------------------------------
__global__ __launch_bounds__(256, 2) void hog_cells_kernel(const float* __restrict__ x)
{
    __shared__ float sm[66][68];        // gray halo tile (stride 68 -> 16B aligned rows)
    __shared__ float shist[NORI][64];   // per-cell hist staging for coalesced store

    const int tx = blockIdx.x;
    const int ty = blockIdx.y;
    const int b  = blockIdx.z;
    const int tid = threadIdx.x;
    const int oy = ty * 64;
    const int ox = tx * 64;

    // ---- Phase 1a: interior 64x64 gray, vectorized (3x LDG.128 -> 4 pixels) ----
#pragma unroll
    for (int it = 0; it < 4; it++) {
        const int idx = it * 256 + tid;        // 0..1023
        const int row = idx >> 4;              // 0..63
        const int g   = idx & 15;              // group of 4 pixels
        const size_t off = ((size_t)((b * IMH) + oy + row) * IMW + ox + g * 4) * 3;
        const float4* p4 = reinterpret_cast<const float4*>(x + off);
        const float4 f0 = p4[0];
        const float4 f1 = p4[1];
        const float4 f2 = p4[2];
        const float g0 = 0.2125f * f0.x + 0.7154f * f0.y + 0.0721f * f0.z;
        const float g1 = 0.2125f * f0.w + 0.7154f * f1.x + 0.0721f * f1.y;
        const float g2 = 0.2125f * f1.z + 0.7154f * f1.w + 0.0721f * f2.x;
        const float g3 = 0.2125f * f2.y + 0.7154f * f2.z + 0.0721f * f2.w;
        float* d = &sm[row + 1][g * 4 + 1];
        d[0] = g0; d[1] = g1; d[2] = g2; d[3] = g3;
    }

    // ---- Phase 1b: halo (mirror at image borders => zero central diff) ----
    {
        const int side = tid >> 6;     // 0:top 1:bottom 2:left 3:right
        const int j = tid & 63;
        int h, w, lr, lc;
        if (side == 0)      { h = oy - 1;  w = ox + j;  lr = 0;      lc = j + 1; }
        else if (side == 1) { h = oy + 64; w = ox + j;  lr = 65;     lc = j + 1; }
        else if (side == 2) { h = oy + j;  w = ox - 1;  lr = j + 1;  lc = 0;     }
        else                { h = oy + j;  w = ox + 64; lr = j + 1;  lc = 65;    }
        h = (h < 0) ? 1 : ((h > IMH - 1) ? IMH - 2 : h);
        w = (w < 0) ? 1 : ((w > IMW - 1) ? IMW - 2 : w);
        const float* p = x + ((size_t)(b * IMH + h) * IMW + w) * 3;
        sm[lr][lc] = 0.2125f * p[0] + 0.7154f * p[1] + 0.0721f * p[2];
    }
    __syncthreads();

    // ---- Phase 2: 4x4 pixel quadrant per thread, all in registers ----
    const int cell = tid >> 2;
    const int sub  = tid & 3;
    const int cy = cell >> 3;
    const int cx = cell & 7;
    const int py0 = cy * 8 + (sub >> 1) * 4;   // multiple of 4
    const int px0 = cx * 8 + (sub & 1) * 4;    // multiple of 4

    // 6x6 gray patch via 6x (LDS.128 + LDS.64)
    float P[6][6];
#pragma unroll
    for (int r = 0; r < 6; r++) {
        const float4 a = *reinterpret_cast<const float4*>(&sm[py0 + r][px0]);
        const float2 e = *reinterpret_cast<const float2*>(&sm[py0 + r][px0 + 4]);
        P[r][0] = a.x; P[r][1] = a.y; P[r][2] = a.z; P[r][3] = a.w;
        P[r][4] = e.x; P[r][5] = e.y;
    }

    float c[NORI];
#pragma unroll
    for (int o = 0; o < NORI; o++) c[o] = 0.0f;

#pragma unroll
    for (int dy = 0; dy < 4; dy++) {
#pragma unroll
        for (int dx = 0; dx < 4; dx++) {
            const float gr = P[dy + 2][dx + 1] - P[dy][dx + 1];
            const float gc = P[dy + 1][dx + 2] - P[dy + 1][dx];
            const float mag = fsqrt_approx(gr * gr + gc * gc);

            // canonicalize to theta in [0,180)
            const bool flip = (gr < 0.0f) || (gr == 0.0f && gc < 0.0f);
            const float yy = flip ? -gr : gr;
            const float xx = flip ? -gc : gc;

            // s_k = r*sin(20k - theta); s_k < 0  <=>  bin >= k  (monotone)
            const float s1 = xx * 0.3420201433f - yy * 0.9396926208f;
            const float s2 = xx * 0.6427876097f - yy * 0.7660444431f;
            const float s3 = xx * 0.8660254038f - yy * 0.5000000000f;
            const float s4 = xx * 0.9848077530f - yy * 0.1736481777f;
            const float s5 = xx * 0.9848077530f + yy * 0.1736481777f;
            const float s6 = xx * 0.8660254038f + yy * 0.5000000000f;
            const float s7 = xx * 0.6427876097f + yy * 0.7660444431f;
            const float s8 = xx * 0.3420201433f + yy * 0.9396926208f;

            c[0] += mag;                       // cumulative counts
            if (s1 < 0.0f) c[1] += mag;
            if (s2 < 0.0f) c[2] += mag;
            if (s3 < 0.0f) c[3] += mag;
            if (s4 < 0.0f) c[4] += mag;
            if (s5 < 0.0f) c[5] += mag;
            if (s6 < 0.0f) c[6] += mag;
            if (s7 < 0.0f) c[7] += mag;
            if (s8 < 0.0f) c[8] += mag;
        }
    }

    // reduce 4 quadrant threads (adjacent lanes) per cell
#pragma unroll
    for (int o = 0; o < NORI; o++) {
        c[o] += __shfl_xor_sync(0xffffffffu, c[o], 1);
        c[o] += __shfl_xor_sync(0xffffffffu, c[o], 2);
    }

    if (sub == 0) {
#pragma unroll
        for (int o = 0; o < NORI - 1; o++)
            shist[o][cell] = (c[o] - c[o + 1]) * 0.015625f;   // hist[o] = c_o - c_{o+1}
        shist[NORI - 1][cell] = c[NORI - 1] * 0.015625f;
    }
    __syncthreads();

    // ---- Phase 3: transposed global store g_hist[b][o][cellY][cellX] ----
    const size_t base = (size_t)b * NORI * NC * NC;
    for (int i = tid; i < NORI * 64; i += 256) {
        const int o  = i >> 6;
        const int cl = i & 63;
        const int cyy = cl >> 3;
        const int cxx = cl & 7;
        g_hist[base + (size_t)o * (NC * NC) + (ty * 8 + cyy) * NC + (tx * 8 + cxx)]
            = shist[o][cl];
    }
}

// ---------------------------------------------------------------------------
// Kernel 2: 2x2 block gather (coalesced per-orientation planes, L2 hits)
//           + double L2-hys normalization + coalesced store via padded smem.
// ---------------------------------------------------------------------------
#define T2 16
__global__ __launch_bounds__(256) void hog_blocks_kernel(float* __restrict__ out)
{
    __shared__ float buf[256 * 37];   // pad 37 -> conflict-free STS

    const int b   = blockIdx.z;
    const int rp0 = blockIdx.y * T2;
    const int cp0 = blockIdx.x * T2;
    const int tid = threadIdx.x;

    const int lr = tid >> 4;
    const int lc = tid & 15;
    const int rp = rp0 + lr;
    const int cp = cp0 + lc;
    const bool valid = (rp < NB) && (cp < NB);
    const int rpc = min(rp, NB - 1);
    const int cpc = min(cp, NB - 1);

    const size_t base = (size_t)b * NORI * NC * NC + (size_t)rpc * NC + cpc;

    float v[36];
    float ss = 1e-10f;   // EPS^2
#pragma unroll
    for (int o = 0; o < NORI; o++) {
        const float* pl = g_hist + base + (size_t)o * (NC * NC);
        const float t00 = pl[0];        // (dr=0,dc=0)
        const float t01 = pl[1];        // (dr=0,dc=1)
        const float t10 = pl[NC];       // (dr=1,dc=0)
        const float t11 = pl[NC + 1];   // (dr=1,dc=1)
        v[o]      = t00;
        v[9 + o]  = t01;
        v[18 + o] = t10;
        v[27 + o] = t11;
        ss += t00 * t00 + t01 * t01 + t10 * t10 + t11 * t11;
    }

    const float n1 = rsqrtf(ss);
    float ss2 = 1e-10f;
#pragma unroll
    for (int j = 0; j < 36; j++) {
        const float t = fminf(v[j] * n1, 0.2f);
        v[j] = t;
        ss2 += t * t;
    }
    const float n2 = rsqrtf(ss2);
    if (valid) {
#pragma unroll
        for (int j = 0; j < 36; j++)
            buf[tid * 37 + j] = v[j] * n2;
    }
    __syncthreads();

    // coalesced store, row by row of the position tile
    const int rows = min(T2, NB - rp0);
    const int cols = min(T2, NB - cp0);
    const int n = cols * 36;
    for (int r = 0; r < rows; r++) {
        const size_t ob = (size_t)b * OUT_PER_B + ((size_t)(rp0 + r) * NB + cp0) * 36;
        const float* src = &buf[r * T2 * 37];
        for (int i = tid; i < n; i += 256) {
            const int cpos = i / 36;
            const int j = i - cpos * 36;
            out[ob + i] = src[cpos * 37 + j];
        }
    }
}

extern "C" void kernel_launch(void* const* d_in, const int* in_sizes, int n_in,
                              void* d_out, int out_size)
{
    const float* x = (const float*)d_in[0];
    float* out = (float*)d_out;

    dim3 g1(IMW / 64, IMH / 64, BATCH);                       // (8, 8, 64)
    hog_cells_kernel<<<g1, 256>>>(x);

    dim3 g2((NB + T2 - 1) / T2, (NB + T2 - 1) / T2, BATCH);   // (4, 4, 64)
    hog_blocks_kernel<<<g2, 256>>>(out);
}

// round 5
// speedup vs baseline: 2.2875x; 1.4915x over previous
#include <cuda_runtime.h>
#include <math.h>

#define BATCH 64
#define IMH 512
#define IMW 512
#define NC 64
#define NORI 9
#define NB 63
#define OUT_PER_B (NB*NB*2*2*NORI)   // 142884
#define NPOS (NB*NB)                 // 3969

// Transposed cell histogram scratch: [B][9][NC][NC] = 9.4 MB (L2-resident)
__device__ float g_hist[(size_t)BATCH * NORI * NC * NC];

__device__ __forceinline__ float fsqrt_approx(float v) {
    float r;
    asm("sqrt.approx.f32 %0, %1;" : "=f"(r) : "f"(v));
    return r;
}

// ---------------------------------------------------------------------------
// Kernel 1: gray -> gradients -> orientation cumsum -> 8x8 cell histograms
// Tile = 32x64 pixels (4x8 cells), 256 threads, thread = 2x4 pixel patch.
// Small smem (9.2KB) + low regs -> 4 CTAs / 32 warps per SM for latency hiding.
// ---------------------------------------------------------------------------
__global__ __launch_bounds__(256, 4) void hog_cells_kernel(const float* __restrict__ x)
{
    __shared__ float sm[34][68];        // 34x66 gray halo tile, padded stride
    __shared__ float shist[NORI][32];   // per-cell hist staging

    const int bx = blockIdx.x;          // 0..7   (64-px cols)
    const int by = blockIdx.y;          // 0..15  (32-px rows)
    const int b  = blockIdx.z;
    const int tid = threadIdx.x;
    const int oy = by * 32;
    const int ox = bx * 64;

    // ---- interior 32x64 gray, vectorized: 3x LDG.128 -> 4 pixels ----
#pragma unroll
    for (int it = 0; it < 2; it++) {
        const int idx = it * 256 + tid;        // 0..511
        const int row = idx >> 4;              // 0..31
        const int g   = idx & 15;              // group of 4 pixels
        const size_t off = ((size_t)((b * IMH) + oy + row) * IMW + ox + g * 4) * 3;
        const float4* p4 = reinterpret_cast<const float4*>(x + off);
        const float4 f0 = p4[0];
        const float4 f1 = p4[1];
        const float4 f2 = p4[2];
        float* d = &sm[row + 1][g * 4 + 1];
        d[0] = 0.2125f * f0.x + 0.7154f * f0.y + 0.0721f * f0.z;
        d[1] = 0.2125f * f0.w + 0.7154f * f1.x + 0.0721f * f1.y;
        d[2] = 0.2125f * f1.z + 0.7154f * f1.w + 0.0721f * f2.x;
        d[3] = 0.2125f * f2.y + 0.7154f * f2.z + 0.0721f * f2.w;
    }

    // ---- halo ring (196 px), mirror at image borders => zero central diff ----
    if (tid < 196) {
        int lr, lc;
        if (tid < 66)       { lr = 0;         lc = tid;       }
        else if (tid < 132) { lr = 33;        lc = tid - 66;  }
        else if (tid < 164) { lr = tid - 131; lc = 0;         }
        else                { lr = tid - 163; lc = 65;        }
        int h = oy - 1 + lr;
        int w = ox - 1 + lc;
        h = (h < 0) ? 1 : ((h > IMH - 1) ? IMH - 2 : h);
        w = (w < 0) ? 1 : ((w > IMW - 1) ? IMW - 2 : w);
        const float* p = x + ((size_t)(b * IMH + h) * IMW + w) * 3;
        sm[lr][lc] = 0.2125f * p[0] + 0.7154f * p[1] + 0.0721f * p[2];
    }
    __syncthreads();

    // ---- 2x4 pixel patch per thread (8 threads per 8x8 cell) ----
    const int cell = tid >> 3;          // 0..31  (4 rows x 8 cols of cells)
    const int sub  = tid & 7;
    const int cy = cell >> 3;           // 0..3
    const int cx = cell & 7;            // 0..7
    const int py0 = cy * 8 + (sub >> 1) * 2;   // tile-local pixel row base
    const int px0 = cx * 8 + (sub & 1) * 4;    // multiple of 4

    // 4x6 gray patch via 4x (LDS.128 + LDS.64); sm col = pixel col + 1
    float P[4][6];
#pragma unroll
    for (int r = 0; r < 4; r++) {
        const float4 a = *reinterpret_cast<const float4*>(&sm[py0 + r][px0]);
        const float2 e = *reinterpret_cast<const float2*>(&sm[py0 + r][px0 + 4]);
        P[r][0] = a.x; P[r][1] = a.y; P[r][2] = a.z; P[r][3] = a.w;
        P[r][4] = e.x; P[r][5] = e.y;
    }

    float c[NORI];
#pragma unroll
    for (int o = 0; o < NORI; o++) c[o] = 0.0f;

#pragma unroll
    for (int dy = 0; dy < 2; dy++) {
#pragma unroll
        for (int dx = 0; dx < 4; dx++) {
            const float gr = P[dy + 2][dx + 1] - P[dy][dx + 1];
            const float gc = P[dy + 1][dx + 2] - P[dy + 1][dx];
            const float mag = fsqrt_approx(gr * gr + gc * gc);

            // canonicalize to theta in [0,180)
            const bool flip = (gr < 0.0f) || (gr == 0.0f && gc < 0.0f);
            const float yy = flip ? -gr : gr;
            const float xx = flip ? -gc : gc;

            // s_k = r*sin(20k - theta); s_k < 0  <=>  bin >= k  (monotone)
            const float s1 = xx * 0.3420201433f - yy * 0.9396926208f;
            const float s2 = xx * 0.6427876097f - yy * 0.7660444431f;
            const float s3 = xx * 0.8660254038f - yy * 0.5000000000f;
            const float s4 = xx * 0.9848077530f - yy * 0.1736481777f;
            const float s5 = xx * 0.9848077530f + yy * 0.1736481777f;
            const float s6 = xx * 0.8660254038f + yy * 0.5000000000f;
            const float s7 = xx * 0.6427876097f + yy * 0.7660444431f;
            const float s8 = xx * 0.3420201433f + yy * 0.9396926208f;

            c[0] += mag;
            if (s1 < 0.0f) c[1] += mag;
            if (s2 < 0.0f) c[2] += mag;
            if (s3 < 0.0f) c[3] += mag;
            if (s4 < 0.0f) c[4] += mag;
            if (s5 < 0.0f) c[5] += mag;
            if (s6 < 0.0f) c[6] += mag;
            if (s7 < 0.0f) c[7] += mag;
            if (s8 < 0.0f) c[8] += mag;
        }
    }

    // reduce 8 patch threads per cell (consecutive lanes)
#pragma unroll
    for (int o = 0; o < NORI; o++) {
        c[o] += __shfl_xor_sync(0xffffffffu, c[o], 1);
        c[o] += __shfl_xor_sync(0xffffffffu, c[o], 2);
        c[o] += __shfl_xor_sync(0xffffffffu, c[o], 4);
    }

    if (sub == 0) {
#pragma unroll
        for (int o = 0; o < NORI - 1; o++)
            shist[o][cell] = (c[o] - c[o + 1]) * 0.015625f;   // hist[o] = c_o - c_{o+1}
        shist[NORI - 1][cell] = c[NORI - 1] * 0.015625f;
    }
    __syncthreads();

    // ---- transposed global store: g_hist[b][o][cellY][cellX] ----
    const size_t base = (size_t)b * NORI * NC * NC;
    if (tid < NORI * 32 + 0) { }   // (288 elems handled below)
    for (int i = tid; i < NORI * 32; i += 256) {
        const int o   = i >> 5;
        const int cl  = i & 31;
        const int cyy = cl >> 3;
        const int cxx = cl & 7;
        g_hist[base + (size_t)o * (NC * NC) + (by * 4 + cyy) * NC + (bx * 8 + cxx)]
            = shist[o][cl];
    }
}

// ---------------------------------------------------------------------------
// Kernel 2: 4 threads per block position (1 cell each), shfl-reduced norms,
// conflict-free smem staging (4p+9q bijective mod 32), float4 coalesced out.
// ---------------------------------------------------------------------------
__global__ __launch_bounds__(256) void hog_blocks_kernel(float* __restrict__ out)
{
    __shared__ float buf[64 * 36];     // 9216 B, position-major, output order

    const int b   = blockIdx.y;
    const int p0  = blockIdx.x * 64;
    const int tid = threadIdx.x;

    const int lp = tid >> 2;           // local position 0..63
    const int q  = tid & 3;            // which cell of the 2x2 block
    const int p  = p0 + lp;
    const bool valid = (p < NPOS);
    const int pc = valid ? p : NPOS - 1;
    const int rp = pc / NB;
    const int cp = pc - rp * NB;
    const int dr = q >> 1;
    const int dc = q & 1;

    const float* hp = g_hist + (size_t)b * NORI * NC * NC + (rp + dr) * NC + (cp + dc);

    float v[NORI];
    float ss = 0.25e-10f;              // EPS^2 split across 4 lanes
#pragma unroll
    for (int o = 0; o < NORI; o++) {
        const float t = hp[(size_t)o * (NC * NC)];
        v[o] = t;
        ss += t * t;
    }
    ss += __shfl_xor_sync(0xffffffffu, ss, 1);
    ss += __shfl_xor_sync(0xffffffffu, ss, 2);

    const float n1 = rsqrtf(ss);
    float ss2 = 0.25e-10f;
#pragma unroll
    for (int o = 0; o < NORI; o++) {
        const float t = fminf(v[o] * n1, 0.2f);
        v[o] = t;
        ss2 += t * t;
    }
    ss2 += __shfl_xor_sync(0xffffffffu, ss2, 1);
    ss2 += __shfl_xor_sync(0xffffffffu, ss2, 2);

    const float n2 = rsqrtf(ss2);
    if (valid) {
        float* d = &buf[lp * 36 + q * NORI];
#pragma unroll
        for (int o = 0; o < NORI; o++)
            d[o] = v[o] * n2;
    }
    __syncthreads();

    // coalesced float4 copy-out of contiguous [p0*36 .. ) chunk
    const int npos = min(64, NPOS - p0);
    const int n4 = npos * 9;           // npos*36/4
    const float4* s4 = reinterpret_cast<const float4*>(buf);
    float4* o4 = reinterpret_cast<float4*>(out + (size_t)b * OUT_PER_B + (size_t)p0 * 36);
    for (int i = tid; i < n4; i += 256)
        o4[i] = s4[i];
}

extern "C" void kernel_launch(void* const* d_in, const int* in_sizes, int n_in,
                              void* d_out, int out_size)
{
    const float* x = (const float*)d_in[0];
    float* out = (float*)d_out;

    dim3 g1(IMW / 64, IMH / 32, BATCH);          // (8, 16, 64) = 8192 CTAs
    hog_cells_kernel<<<g1, 256>>>(x);

    dim3 g2((NPOS + 63) / 64, BATCH);            // (63, 64)
    hog_blocks_kernel<<<g2, 256>>>(out);
}

// round 6
// speedup vs baseline: 2.4210x; 1.0584x over previous
#include <cuda_runtime.h>
#include <math.h>

#define BATCH 64
#define IMH 512
#define IMW 512
#define NC 64
#define NORI 9
#define NB 63
#define OUT_PER_B (NB*NB*2*2*NORI)   // 142884
#define NPOS (NB*NB)                 // 3969

// Transposed cell histogram scratch: [B][9][NC][NC] = 9.4 MB (L2-resident)
__device__ float g_hist[(size_t)BATCH * NORI * NC * NC];

__device__ __forceinline__ float fsqrt_approx(float v) {
    float r;
    asm("sqrt.approx.f32 %0, %1;" : "=f"(r) : "f"(v));
    return r;
}

// ---------------------------------------------------------------------------
// Kernel 1: gray -> gradients -> orientation cumsum -> 8x8 cell histograms
// Tile = 32x64 pixels (4x8 cells), 256 threads, thread = 2x4 pixel patch.
// 5 CTAs/SM (40 warps) for latency hiding; all 9 global loads per thread are
// unconditional and front-batched for max MLP.
// ---------------------------------------------------------------------------
__global__ __launch_bounds__(256, 5) void hog_cells_kernel(const float* __restrict__ x)
{
    __shared__ float sm[34][68];        // 34x66 gray halo tile, padded stride
    __shared__ float shist[NORI][32];   // per-cell hist staging

    const int bx = blockIdx.x;          // 0..7   (64-px cols)
    const int by = blockIdx.y;          // 0..15  (32-px rows)
    const int b  = blockIdx.z;
    const int tid = threadIdx.x;
    const int oy = by * 32;
    const int ox = bx * 64;

    // ---- interior 32x64 gray: 2x (3x LDG.128 -> 4 pixels) ----
    const int row0 = tid >> 4;              // 0..15
    const int g0   = tid & 15;
    const size_t offA = ((size_t)((b * IMH) + oy + row0) * IMW + ox + g0 * 4) * 3;
    const size_t offB = ((size_t)((b * IMH) + oy + row0 + 16) * IMW + ox + g0 * 4) * 3;
    const float4* pA = reinterpret_cast<const float4*>(x + offA);
    const float4* pB = reinterpret_cast<const float4*>(x + offB);

    // ---- halo ring (196 px): unconditional load, predicated store ----
    const int ht = (tid < 196) ? tid : 195;
    int lr, lc;
    if (ht < 66)       { lr = 0;        lc = ht;       }
    else if (ht < 132) { lr = 33;       lc = ht - 66;  }
    else if (ht < 164) { lr = ht - 131; lc = 0;        }
    else               { lr = ht - 163; lc = 65;       }
    int hh = oy - 1 + lr;
    int hw = ox - 1 + lc;
    hh = (hh < 0) ? 1 : ((hh > IMH - 1) ? IMH - 2 : hh);
    hw = (hw < 0) ? 1 : ((hw > IMW - 1) ? IMW - 2 : hw);
    const float* hp = x + ((size_t)(b * IMH + hh) * IMW + hw) * 3;

    // issue all loads back-to-back
    const float4 a0 = pA[0], a1 = pA[1], a2 = pA[2];
    const float4 b0 = pB[0], b1 = pB[1], b2 = pB[2];
    const float  h0 = hp[0], h1 = hp[1], h2 = hp[2];

    {
        float* d = &sm[row0 + 1][g0 * 4 + 1];
        d[0] = 0.2125f * a0.x + 0.7154f * a0.y + 0.0721f * a0.z;
        d[1] = 0.2125f * a0.w + 0.7154f * a1.x + 0.0721f * a1.y;
        d[2] = 0.2125f * a1.z + 0.7154f * a1.w + 0.0721f * a2.x;
        d[3] = 0.2125f * a2.y + 0.7154f * a2.z + 0.0721f * a2.w;
        float* e = &sm[row0 + 17][g0 * 4 + 1];
        e[0] = 0.2125f * b0.x + 0.7154f * b0.y + 0.0721f * b0.z;
        e[1] = 0.2125f * b0.w + 0.7154f * b1.x + 0.0721f * b1.y;
        e[2] = 0.2125f * b1.z + 0.7154f * b1.w + 0.0721f * b2.x;
        e[3] = 0.2125f * b2.y + 0.7154f * b2.z + 0.0721f * b2.w;
    }
    if (tid < 196)
        sm[lr][lc] = 0.2125f * h0 + 0.7154f * h1 + 0.0721f * h2;
    __syncthreads();

    // ---- 2x4 pixel patch per thread (8 threads per 8x8 cell) ----
    const int cell = tid >> 3;          // 0..31  (4 rows x 8 cols of cells)
    const int sub  = tid & 7;
    const int cy = cell >> 3;           // 0..3
    const int cx = cell & 7;            // 0..7
    const int py0 = cy * 8 + (sub >> 1) * 2;
    const int px0 = cx * 8 + (sub & 1) * 4;    // multiple of 4

    // 4x6 gray patch via 4x (LDS.128 + LDS.64)
    float P[4][6];
#pragma unroll
    for (int r = 0; r < 4; r++) {
        const float4 a = *reinterpret_cast<const float4*>(&sm[py0 + r][px0]);
        const float2 e = *reinterpret_cast<const float2*>(&sm[py0 + r][px0 + 4]);
        P[r][0] = a.x; P[r][1] = a.y; P[r][2] = a.z; P[r][3] = a.w;
        P[r][4] = e.x; P[r][5] = e.y;
    }

    float c[NORI];
#pragma unroll
    for (int o = 0; o < NORI; o++) c[o] = 0.0f;

#pragma unroll
    for (int dy = 0; dy < 2; dy++) {
#pragma unroll
        for (int dx = 0; dx < 4; dx++) {
            const float gr = P[dy + 2][dx + 1] - P[dy][dx + 1];
            const float gc = P[dy + 1][dx + 2] - P[dy + 1][dx];
            const float mag = fsqrt_approx(gr * gr + gc * gc);

            // canonicalize to theta in [0,180)
            const bool flip = (gr < 0.0f) || (gr == 0.0f && gc < 0.0f);
            const float yy = flip ? -gr : gr;
            const float xx = flip ? -gc : gc;

            // s_k = r*sin(20k - theta); s_k < 0  <=>  bin >= k  (monotone)
            const float s1 = xx * 0.3420201433f - yy * 0.9396926208f;
            const float s2 = xx * 0.6427876097f - yy * 0.7660444431f;
            const float s3 = xx * 0.8660254038f - yy * 0.5000000000f;
            const float s4 = xx * 0.9848077530f - yy * 0.1736481777f;
            const float s5 = xx * 0.9848077530f + yy * 0.1736481777f;
            const float s6 = xx * 0.8660254038f + yy * 0.5000000000f;
            const float s7 = xx * 0.6427876097f + yy * 0.7660444431f;
            const float s8 = xx * 0.3420201433f + yy * 0.9396926208f;

            c[0] += mag;
            if (s1 < 0.0f) c[1] += mag;
            if (s2 < 0.0f) c[2] += mag;
            if (s3 < 0.0f) c[3] += mag;
            if (s4 < 0.0f) c[4] += mag;
            if (s5 < 0.0f) c[5] += mag;
            if (s6 < 0.0f) c[6] += mag;
            if (s7 < 0.0f) c[7] += mag;
            if (s8 < 0.0f) c[8] += mag;
        }
    }

    // reduce 8 patch threads per cell (consecutive lanes)
#pragma unroll
    for (int o = 0; o < NORI; o++) {
        c[o] += __shfl_xor_sync(0xffffffffu, c[o], 1);
        c[o] += __shfl_xor_sync(0xffffffffu, c[o], 2);
        c[o] += __shfl_xor_sync(0xffffffffu, c[o], 4);
    }

    if (sub == 0) {
#pragma unroll
        for (int o = 0; o < NORI - 1; o++)
            shist[o][cell] = (c[o] - c[o + 1]) * 0.015625f;   // hist[o] = c_o - c_{o+1}
        shist[NORI - 1][cell] = c[NORI - 1] * 0.015625f;
    }
    __syncthreads();

    // ---- transposed global store: g_hist[b][o][cellY][cellX] ----
    const size_t base = (size_t)b * NORI * NC * NC;
    for (int i = tid; i < NORI * 32; i += 256) {
        const int o   = i >> 5;
        const int cl  = i & 31;
        const int cyy = cl >> 3;
        const int cxx = cl & 7;
        g_hist[base + (size_t)o * (NC * NC) + (by * 4 + cyy) * NC + (bx * 8 + cxx)]
            = shist[o][cl];
    }
}

// ---------------------------------------------------------------------------
// Kernel 2: 4 threads per block position (1 cell each), shfl-reduced norms,
// conflict-free smem staging (4p+9q bijective mod 32), float4 coalesced out.
// ---------------------------------------------------------------------------
__global__ __launch_bounds__(256) void hog_blocks_kernel(float* __restrict__ out)
{
    __shared__ float buf[64 * 36];     // 9216 B, position-major, output order

    const int b   = blockIdx.y;
    const int p0  = blockIdx.x * 64;
    const int tid = threadIdx.x;

    const int lp = tid >> 2;           // local position 0..63
    const int q  = tid & 3;            // which cell of the 2x2 block
    const int p  = p0 + lp;
    const bool valid = (p < NPOS);
    const int pc = valid ? p : NPOS - 1;
    const int rp = pc / NB;
    const int cp = pc - rp * NB;
    const int dr = q >> 1;
    const int dc = q & 1;

    const float* hp = g_hist + (size_t)b * NORI * NC * NC + (rp + dr) * NC + (cp + dc);

    float v[NORI];
    float ss = 0.25e-10f;              // EPS^2 split across 4 lanes
#pragma unroll
    for (int o = 0; o < NORI; o++) {
        const float t = hp[(size_t)o * (NC * NC)];
        v[o] = t;
        ss += t * t;
    }
    ss += __shfl_xor_sync(0xffffffffu, ss, 1);
    ss += __shfl_xor_sync(0xffffffffu, ss, 2);

    const float n1 = rsqrtf(ss);
    float ss2 = 0.25e-10f;
#pragma unroll
    for (int o = 0; o < NORI; o++) {
        const float t = fminf(v[o] * n1, 0.2f);
        v[o] = t;
        ss2 += t * t;
    }
    ss2 += __shfl_xor_sync(0xffffffffu, ss2, 1);
    ss2 += __shfl_xor_sync(0xffffffffu, ss2, 2);

    const float n2 = rsqrtf(ss2);
    if (valid) {
        float* d = &buf[lp * 36 + q * NORI];
#pragma unroll
        for (int o = 0; o < NORI; o++)
            d[o] = v[o] * n2;
    }
    __syncthreads();

    // coalesced float4 copy-out of contiguous [p0*36 .. ) chunk
    const int npos = min(64, NPOS - p0);
    const int n4 = npos * 9;           // npos*36/4
    const float4* s4 = reinterpret_cast<const float4*>(buf);
    float4* o4 = reinterpret_cast<float4*>(out + (size_t)b * OUT_PER_B + (size_t)p0 * 36);
    for (int i = tid; i < n4; i += 256)
        o4[i] = s4[i];
}

extern "C" void kernel_launch(void* const* d_in, const int* in_sizes, int n_in,
                              void* d_out, int out_size)
{
    const float* x = (const float*)d_in[0];
    float* out = (float*)d_out;

    dim3 g1(IMW / 64, IMH / 32, BATCH);          // (8, 16, 64) = 8192 CTAs
    hog_cells_kernel<<<g1, 256>>>(x);

    dim3 g2((NPOS + 63) / 64, BATCH);            // (63, 64)
    hog_blocks_kernel<<<g2, 256>>>(out);
}